// round 2
// baseline (speedup 1.0000x reference)
#include <cuda_runtime.h>

#define BB   64
#define CIN  12
#define LL   4096
#define TT   20
#define NC1  64
#define NC2  64
#define NCLS 4

// spike bits: 2x u32 per (b,t,l)  => 41.9 MB scratch
__device__ unsigned int g_s1[BB * TT * LL * 2];
// transposed conv2 weights: [c1][k][c2]
__device__ float g_w2t[NC1 * 3 * NC2];
// per (b,c2) spike counts
__device__ float g_pool[BB * NC2];

// ---------------------------------------------------------------------------
// k_pre: zero pool + build transposed w2
// ---------------------------------------------------------------------------
__global__ void k_pre(const float* __restrict__ w2) {
    int i = blockIdx.x * blockDim.x + threadIdx.x;
    if (i < BB * NC2) g_pool[i] = 0.0f;
    if (i < NC1 * 3 * NC2) {
        int c2 = i & 63;
        int k  = (i >> 6) % 3;
        int c1 = i / 192;
        g_w2t[i] = w2[c2 * (NC1 * 3) + c1 * 3 + k];
    }
}

// ---------------------------------------------------------------------------
// k_conv1: conv1 + threshold -> bit-packed spikes (no temporal state: TAU1=1)
// block = (l-tile of 32, b); 256 threads = 8 warps.
// warp handles half the c1 channels (lane = channel); tasks = (t-group, l).
// ---------------------------------------------------------------------------
__global__ __launch_bounds__(256) void k_conv1(
        const float* __restrict__ x,
        const float* __restrict__ w1,
        const float* __restrict__ b1,
        const float* __restrict__ pgain,
        const float* __restrict__ pth1) {
    __shared__ __align__(16) float s_x[CIN][34][TT];   // 32.6 KB

    const int l0  = blockIdx.x * 32;
    const int b   = blockIdx.y;
    const int tid = threadIdx.x;

    // stage x: (l,t) is contiguous in global per channel -> coalesced
    for (int i = tid; i < CIN * 34 * TT; i += 256) {
        int c   = i / (34 * TT);
        int rem = i % (34 * TT);
        int lx  = rem / TT;
        int t   = rem % TT;
        int gl  = l0 - 1 + lx;
        float v = 0.0f;
        if (gl >= 0 && gl < LL)
            v = x[((size_t)(b * CIN + c) * LL + gl) * TT + t];
        s_x[c][lx][t] = v;
    }

    const int w    = tid >> 5;
    const int lane = tid & 31;
    const int half = w & 1;
    const int pair = w >> 1;
    const int c1   = half * 32 + lane;

    // weights for this channel in registers
    float wr[CIN][3];
#pragma unroll
    for (int c = 0; c < CIN; c++)
#pragma unroll
        for (int k = 0; k < 3; k++)
            wr[c][k] = w1[c1 * (CIN * 3) + c * 3 + k];
    const float bias = b1[c1];
    const float gain = *pgain;
    const float th1  = *pth1;

    __syncthreads();

    // 160 tasks = 5 t-groups x 32 l positions, split over 4 warp-pairs
    for (int task = pair; task < 160; task += 4) {
        int ll = task & 31;
        int tg = task >> 5;
        int t0 = tg * 4;
        float a[4] = {0.f, 0.f, 0.f, 0.f};
#pragma unroll
        for (int c = 0; c < CIN; c++) {
#pragma unroll
            for (int k = 0; k < 3; k++) {
                float4 xv = *(const float4*)&s_x[c][ll + k][t0];
                float  wv = wr[c][k];
                a[0] += xv.x * wv;
                a[1] += xv.y * wv;
                a[2] += xv.z * wv;
                a[3] += xv.w * wv;
            }
        }
        int gl = l0 + ll;
#pragma unroll
        for (int j = 0; j < 4; j++) {
            float i1 = (a[j] + bias) * gain;
            unsigned m = __ballot_sync(0xffffffffu, i1 >= th1);
            if (lane == 0)
                g_s1[((size_t)(b * TT + (t0 + j)) * LL + gl) * 2 + half] = m;
        }
    }
}

// ---------------------------------------------------------------------------
// k_snn: conv2 + v2 LIF recurrence + spike counting.
// block = (l-tile of 64, b); 256 threads; thread = (c2, 16-l strip).
// v2/cnt live in registers across the sequential t loop.
// ---------------------------------------------------------------------------
__global__ __launch_bounds__(256) void k_snn(
        const float* __restrict__ b2,
        const float* __restrict__ pgain,
        const float* __restrict__ pth2) {
    __shared__ __align__(16) float s1f[NC1][72];   // 18.4 KB (4-pad front)

    const int l0  = blockIdx.x * 64;
    const int b   = blockIdx.y;
    const int tid = threadIdx.x;

    const int w    = tid >> 5;
    const int lane = tid & 31;
    const int c2   = (w & 1) * 32 + lane;
    const int ls   = (w >> 1) * 16;

    const float gain   = *pgain;
    const float th2    = *pth2;
    const float bia    = b2[c2];
    const float invtau = 1.0f / 0.9f;

    float v2[16], cnt[16];
#pragma unroll
    for (int j = 0; j < 16; j++) { v2[j] = 0.0f; cnt[j] = 0.0f; }

    for (int t = 0; t < TT; t++) {
        // decode spike bits -> float tile covering gl in [l0-1, l0+65)
        for (int j = tid; j < 132; j += 256) {
            int l_off = j >> 1;
            int hh    = j & 1;
            int gl    = l0 - 1 + l_off;
            unsigned m = 0;
            if (gl >= 0 && gl < LL)
                m = g_s1[((size_t)(b * TT + t) * LL + gl) * 2 + hh];
#pragma unroll
            for (int bit = 0; bit < 32; bit++)
                s1f[hh * 32 + bit][4 + l_off] = (float)((m >> bit) & 1u);
        }
        __syncthreads();

        float sum[16];
#pragma unroll
        for (int j = 0; j < 16; j++) sum[j] = 0.0f;

        for (int c1 = 0; c1 < NC1; c1++) {
            const float* row = &s1f[c1][ls + 4];     // 16B aligned
            float4 q0 = *(const float4*)(row);
            float4 q1 = *(const float4*)(row + 4);
            float4 q2 = *(const float4*)(row + 8);
            float4 q3 = *(const float4*)(row + 12);
            float4 q4 = *(const float4*)(row + 16);
            float r[20] = {q0.x, q0.y, q0.z, q0.w,  q1.x, q1.y, q1.z, q1.w,
                           q2.x, q2.y, q2.z, q2.w,  q3.x, q3.y, q3.z, q3.w,
                           q4.x, q4.y, q4.z, q4.w};
            float w0 = __ldg(&g_w2t[(c1 * 3 + 0) * NC2 + c2]);
            float w1v = __ldg(&g_w2t[(c1 * 3 + 1) * NC2 + c2]);
            float w2v = __ldg(&g_w2t[(c1 * 3 + 2) * NC2 + c2]);
#pragma unroll
            for (int j = 0; j < 16; j++)
                sum[j] += r[j] * w0 + r[j + 1] * w1v + r[j + 2] * w2v;
        }

#pragma unroll
        for (int j = 0; j < 16; j++) {
            float i2 = (sum[j] + bia) * gain;
            v2[j] += (i2 - v2[j]) * invtau;
            if (v2[j] >= th2) { cnt[j] += 1.0f; v2[j] = 0.0f; }
        }
        __syncthreads();
    }

    float tot = 0.0f;
#pragma unroll
    for (int j = 0; j < 16; j++) tot += cnt[j];
    atomicAdd(&g_pool[b * NC2 + c2], tot);   // integer-valued -> exact
}

// ---------------------------------------------------------------------------
// k_fc: pooled = counts / (T*L); logits = pooled @ fc_w.T + fc_b
// ---------------------------------------------------------------------------
__global__ void k_fc(const float* __restrict__ fw,
                     const float* __restrict__ fb,
                     float* __restrict__ out) {
    int tid = threadIdx.x;
    int b = tid >> 2;
    int n = tid & 3;
    const float sc = 1.0f / (float)(TT * LL);
    float s = fb[n];
#pragma unroll
    for (int c = 0; c < NC2; c++)
        s += (g_pool[b * NC2 + c] * sc) * fw[n * NC2 + c];
    out[b * NCLS + n] = s;
}

// ---------------------------------------------------------------------------
extern "C" void kernel_launch(void* const* d_in, const int* in_sizes, int n_in,
                              void* d_out, int out_size) {
    const float* x    = (const float*)d_in[0];
    const float* w1   = (const float*)d_in[1];
    const float* b1   = (const float*)d_in[2];
    const float* w2   = (const float*)d_in[3];
    const float* b2   = (const float*)d_in[4];
    const float* gain = (const float*)d_in[5];
    const float* th1  = (const float*)d_in[6];
    const float* th2  = (const float*)d_in[7];
    const float* fw   = (const float*)d_in[8];
    const float* fb   = (const float*)d_in[9];
    float* out = (float*)d_out;

    k_pre<<<48, 256>>>(w2);

    dim3 g1(LL / 32, BB);
    k_conv1<<<g1, 256>>>(x, w1, b1, gain, th1);

    dim3 g2(LL / 64, BB);
    k_snn<<<g2, 256>>>(b2, gain, th2);

    k_fc<<<1, 256>>>(fw, fb, out);
}

// round 3
// speedup vs baseline: 2.0261x; 2.0261x over previous
#include <cuda_runtime.h>

#define BB   64
#define CIN  12
#define LL   4096
#define TT   20
#define NC1  64
#define NC2  64
#define NCLS 4

typedef unsigned long long ull;

// spike bits: 2x u32 per (b,t,l)  => 41.9 MB scratch
__device__ unsigned int g_s1[BB * TT * LL * 2];
// transposed conv2 weights: [c1][k][c2]
__device__ float g_w2t[NC1 * 3 * NC2];
// per (b,c2) spike counts
__device__ float g_pool[BB * NC2];

// packed f32x2 helpers (Blackwell sm_103a)
#define FMA_F32X2(d, a, b, c) \
    asm("fma.rn.f32x2 %0, %1, %2, %3;" : "=l"(d) : "l"(a), "l"(b), "l"(c))
#define PACK_F32X2(out, lo, hi) \
    asm("mov.b64 %0, {%1, %2};" : "=l"(out) : "f"(lo), "f"(hi))
#define UNPACK_F32X2(lo, hi, in) \
    asm("mov.b64 {%0, %1}, %2;" : "=f"(lo), "=f"(hi) : "l"(in))

// ---------------------------------------------------------------------------
// k_pre: zero pool + build transposed w2
// ---------------------------------------------------------------------------
__global__ void k_pre(const float* __restrict__ w2) {
    int i = blockIdx.x * blockDim.x + threadIdx.x;
    if (i < BB * NC2) g_pool[i] = 0.0f;
    if (i < NC1 * 3 * NC2) {
        int c2 = i & 63;
        int k  = (i >> 6) % 3;
        int c1 = i / 192;
        g_w2t[i] = w2[c2 * (NC1 * 3) + c1 * 3 + k];
    }
}

// ---------------------------------------------------------------------------
// k_conv1: conv1 + threshold -> bit-packed spikes (TAU1=1 => stateless).
// Packed f32x2 over the t axis (t is contiguous in x).
// ---------------------------------------------------------------------------
__global__ __launch_bounds__(256) void k_conv1(
        const float* __restrict__ x,
        const float* __restrict__ w1,
        const float* __restrict__ b1,
        const float* __restrict__ pgain,
        const float* __restrict__ pth1) {
    __shared__ __align__(16) float s_x[CIN][34][TT];   // 32.6 KB

    const int l0  = blockIdx.x * 32;
    const int b   = blockIdx.y;
    const int tid = threadIdx.x;

    // stage x: (l,t) contiguous per channel -> coalesced
    for (int i = tid; i < CIN * 34 * TT; i += 256) {
        int c   = i / (34 * TT);
        int rem = i % (34 * TT);
        int lx  = rem / TT;
        int t   = rem % TT;
        int gl  = l0 - 1 + lx;
        float v = 0.0f;
        if (gl >= 0 && gl < LL)
            v = x[((size_t)(b * CIN + c) * LL + gl) * TT + t];
        s_x[c][lx][t] = v;
    }

    const int w    = tid >> 5;
    const int lane = tid & 31;
    const int half = w & 1;
    const int pair = w >> 1;
    const int c1   = half * 32 + lane;

    // packed broadcast weights: wrp[c][k] = {w, w}
    ull wrp[CIN][3];
#pragma unroll
    for (int c = 0; c < CIN; c++)
#pragma unroll
        for (int k = 0; k < 3; k++) {
            float wv = w1[c1 * (CIN * 3) + c * 3 + k];
            PACK_F32X2(wrp[c][k], wv, wv);
        }
    const float bias = b1[c1];
    const float gain = *pgain;
    const float th1  = *pth1;

    __syncthreads();

    // 160 tasks = 5 t-groups x 32 l positions, split over 4 warp-pairs
    for (int task = pair; task < 160; task += 4) {
        int ll = task & 31;
        int tg = task >> 5;
        int t0 = tg * 4;
        ull a01 = 0ull, a23 = 0ull;   // packed {t0,t0+1}, {t0+2,t0+3}
#pragma unroll
        for (int c = 0; c < CIN; c++) {
#pragma unroll
            for (int k = 0; k < 3; k++) {
                ulonglong2 xq = *(const ulonglong2*)&s_x[c][ll + k][t0];
                FMA_F32X2(a01, xq.x, wrp[c][k], a01);
                FMA_F32X2(a23, xq.y, wrp[c][k], a23);
            }
        }
        float a[4];
        UNPACK_F32X2(a[0], a[1], a01);
        UNPACK_F32X2(a[2], a[3], a23);
        int gl = l0 + ll;
#pragma unroll
        for (int j = 0; j < 4; j++) {
            float i1 = (a[j] + bias) * gain;
            unsigned m = __ballot_sync(0xffffffffu, i1 >= th1);
            if (lane == 0)
                g_s1[((size_t)(b * TT + (t0 + j)) * LL + gl) * 2 + half] = m;
        }
    }
}

// ---------------------------------------------------------------------------
// k_snn: conv2 + v2 LIF recurrence + spike counting.
// Two timesteps per packed f32x2 lane (i2 doesn't depend on v2, so the t-pair
// GEMMs are independent; recurrence applied scalar in the epilogue).
// block = (l-tile of 64, b); thread = (c2, 16-l strip).
// ---------------------------------------------------------------------------
__global__ __launch_bounds__(256) void k_snn(
        const float* __restrict__ b2,
        const float* __restrict__ pgain,
        const float* __restrict__ pth2) {
    // s1p[c1][4 + l_off] = packed {s1[t], s1[t+1]}  (36.9 KB)
    __shared__ __align__(16) ull s1p[NC1][72];

    const int l0  = blockIdx.x * 64;
    const int b   = blockIdx.y;
    const int tid = threadIdx.x;

    const int w    = tid >> 5;
    const int lane = tid & 31;
    const int c2   = (w & 1) * 32 + lane;
    const int ls   = (w >> 1) * 16;

    const float gain   = *pgain;
    const float th2    = *pth2;
    const float bia    = b2[c2];
    const float invtau = 1.0f / 0.9f;

    float v2[16], cnt[16];
#pragma unroll
    for (int j = 0; j < 16; j++) { v2[j] = 0.0f; cnt[j] = 0.0f; }

    for (int t = 0; t < TT; t += 2) {
        // decode spike bits for (t, t+1) -> packed float2 tile, gl in [l0-1, l0+65)
        for (int j = tid; j < 132; j += 256) {
            int l_off = j >> 1;
            int hh    = j & 1;
            int gl    = l0 - 1 + l_off;
            unsigned m0 = 0, m1 = 0;
            if (gl >= 0 && gl < LL) {
                size_t base = ((size_t)(b * TT + t) * LL + gl) * 2 + hh;
                m0 = g_s1[base];
                m1 = g_s1[base + (size_t)LL * 2];
            }
#pragma unroll
            for (int bit = 0; bit < 32; bit++) {
                unsigned lo = ((m0 >> bit) & 1u) * 0x3f800000u;
                unsigned hi = ((m1 >> bit) & 1u) * 0x3f800000u;
                s1p[hh * 32 + bit][4 + l_off] = (ull)lo | ((ull)hi << 32);
            }
        }
        __syncthreads();

        ull sum[16];
#pragma unroll
        for (int j = 0; j < 16; j++) sum[j] = 0ull;

        for (int c1 = 0; c1 < NC1; c1++) {
            const ull* row = &s1p[c1][4 + ls];   // 16B aligned (4+ls even)
            ull rr[18];
#pragma unroll
            for (int i = 0; i < 9; i++) {
                ulonglong2 q = *(const ulonglong2*)&row[2 * i];
                rr[2 * i]     = q.x;
                rr[2 * i + 1] = q.y;
            }
            float w0  = __ldg(&g_w2t[(c1 * 3 + 0) * NC2 + c2]);
            float w1v = __ldg(&g_w2t[(c1 * 3 + 1) * NC2 + c2]);
            float w2v = __ldg(&g_w2t[(c1 * 3 + 2) * NC2 + c2]);
            ull w0p, w1p, w2p;
            PACK_F32X2(w0p, w0, w0);
            PACK_F32X2(w1p, w1v, w1v);
            PACK_F32X2(w2p, w2v, w2v);
#pragma unroll
            for (int j = 0; j < 16; j++) {
                FMA_F32X2(sum[j], rr[j],     w0p, sum[j]);
                FMA_F32X2(sum[j], rr[j + 1], w1p, sum[j]);
                FMA_F32X2(sum[j], rr[j + 2], w2p, sum[j]);
            }
        }

#pragma unroll
        for (int j = 0; j < 16; j++) {
            float s0, s1v;
            UNPACK_F32X2(s0, s1v, sum[j]);
            float i2 = (s0 + bia) * gain;
            v2[j] += (i2 - v2[j]) * invtau;
            if (v2[j] >= th2) { cnt[j] += 1.0f; v2[j] = 0.0f; }
            i2 = (s1v + bia) * gain;
            v2[j] += (i2 - v2[j]) * invtau;
            if (v2[j] >= th2) { cnt[j] += 1.0f; v2[j] = 0.0f; }
        }
        __syncthreads();
    }

    float tot = 0.0f;
#pragma unroll
    for (int j = 0; j < 16; j++) tot += cnt[j];
    atomicAdd(&g_pool[b * NC2 + c2], tot);   // integer-valued -> exact
}

// ---------------------------------------------------------------------------
// k_fc: pooled = counts / (T*L); logits = pooled @ fc_w.T + fc_b
// ---------------------------------------------------------------------------
__global__ void k_fc(const float* __restrict__ fw,
                     const float* __restrict__ fb,
                     float* __restrict__ out) {
    int tid = threadIdx.x;
    int b = tid >> 2;
    int n = tid & 3;
    const float sc = 1.0f / (float)(TT * LL);
    float s = fb[n];
#pragma unroll
    for (int c = 0; c < NC2; c++)
        s += (g_pool[b * NC2 + c] * sc) * fw[n * NC2 + c];
    out[b * NCLS + n] = s;
}

// ---------------------------------------------------------------------------
extern "C" void kernel_launch(void* const* d_in, const int* in_sizes, int n_in,
                              void* d_out, int out_size) {
    const float* x    = (const float*)d_in[0];
    const float* w1   = (const float*)d_in[1];
    const float* b1   = (const float*)d_in[2];
    const float* w2   = (const float*)d_in[3];
    const float* b2   = (const float*)d_in[4];
    const float* gain = (const float*)d_in[5];
    const float* th1  = (const float*)d_in[6];
    const float* th2  = (const float*)d_in[7];
    const float* fw   = (const float*)d_in[8];
    const float* fb   = (const float*)d_in[9];
    float* out = (float*)d_out;

    k_pre<<<48, 256>>>(w2);

    dim3 g1(LL / 32, BB);
    k_conv1<<<g1, 256>>>(x, w1, b1, gain, th1);

    dim3 g2(LL / 64, BB);
    k_snn<<<g2, 256>>>(b2, gain, th2);

    k_fc<<<1, 256>>>(fw, fb, out);
}

// round 5
// speedup vs baseline: 3.8689x; 1.9096x over previous
#include <cuda_runtime.h>
#include <cuda_bf16.h>
#include <cstdint>

#define BB   64
#define CIN  12
#define LL   4096
#define TT   20
#define NC1  64
#define NC2  64
#define NCLS 4
#define NLT  128                 // l positions per tile
#define NTILES (LL / NLT)        // 32

typedef unsigned long long ull;
typedef unsigned int u32;

// spike bits: 2x u32 per (b,t,l)  => 41.9 MB scratch
__device__ u32 g_s1[BB * TT * LL * 2];
// per (b,c2) spike counts
__device__ float g_pool[BB * NC2];
// A fragments in exact mma.sync lane order: [(j*12+s)*32+lane]*4 + r
__device__ u32 g_Ah[4 * 12 * 32 * 4];
__device__ u32 g_Al[4 * 12 * 32 * 4];

// ---------------- packed f32x2 helpers (conv1) ------------------------------
#define FMA_F32X2(d, a, b, c) \
    asm("fma.rn.f32x2 %0, %1, %2, %3;" : "=l"(d) : "l"(a), "l"(b), "l"(c))
#define PACK_F32X2(out, lo, hi) \
    asm("mov.b64 %0, {%1, %2};" : "=l"(out) : "f"(lo), "f"(hi))
#define UNPACK_F32X2(lo, hi, in) \
    asm("mov.b64 {%0, %1}, %2;" : "=f"(lo), "=f"(hi) : "l"(in))

// mma.sync m16n8k16 bf16, fp32 accumulate (baseline PTX, sm_80+)
#define MMA16816(d, a, b) \
    asm volatile("mma.sync.aligned.m16n8k16.row.col.f32.bf16.bf16.f32 " \
        "{%0,%1,%2,%3}, {%4,%5,%6,%7}, {%8,%9}, {%0,%1,%2,%3};" \
        : "+f"((d)[0]), "+f"((d)[1]), "+f"((d)[2]), "+f"((d)[3]) \
        : "r"((a).x), "r"((a).y), "r"((a).z), "r"((a).w), \
          "r"((b).x), "r"((b).y))

// ---------------------------------------------------------------------------
// k_pre: zero pool + build A fragments (hi/lo bf16 split of w2, exact).
// A[m][kap]: m = c2 (hi) / c2 (lo duplicate plane), kap = kk*64 + c1.
// Fragment reg r of m-tile j, k-step s, lane: row = gid + 8*(r&1),
// cols = 16s + 2*tid4 + 8*(r>>1) + {0,1}.
// ---------------------------------------------------------------------------
__global__ void k_pre(const float* __restrict__ w2) {
    int i = blockIdx.x * blockDim.x + threadIdx.x;
    if (i < BB * NC2) g_pool[i] = 0.0f;
    if (i < 4 * 12 * 32 * 4) {
        int r    = i & 3;
        int idx4 = i >> 2;
        int lane = idx4 & 31;
        int js   = idx4 >> 5;
        int s    = js % 12;
        int j    = js / 12;
        int gid  = lane >> 2;
        int tid4 = lane & 3;
        int m    = 16 * j + gid + 8 * (r & 1);
        int kap0 = 16 * s + 2 * tid4 + 8 * (r >> 1);
        u32 hi = 0, lo = 0;
#pragma unroll
        for (int e = 0; e < 2; e++) {
            int kap = kap0 + e;
            int kk  = kap >> 6;
            int c1  = kap & 63;
            float wv = w2[m * (NC1 * 3) + c1 * 3 + kk];
            __nv_bfloat16 bh = __float2bfloat16(wv);
            __nv_bfloat16 bl = __float2bfloat16(wv - __bfloat162float(bh));
            hi |= (u32)__bfloat16_as_ushort(bh) << (16 * e);
            lo |= (u32)__bfloat16_as_ushort(bl) << (16 * e);
        }
        g_Ah[i] = hi;
        g_Al[i] = lo;
    }
}

// ---------------------------------------------------------------------------
// k_conv1: conv1 + threshold -> bit-packed spikes (TAU1=1 => stateless).
// (unchanged: packed f32x2 over contiguous t axis)
// ---------------------------------------------------------------------------
__global__ __launch_bounds__(256) void k_conv1(
        const float* __restrict__ x,
        const float* __restrict__ w1,
        const float* __restrict__ b1,
        const float* __restrict__ pgain,
        const float* __restrict__ pth1) {
    __shared__ __align__(16) float s_x[CIN][34][TT];

    const int l0  = blockIdx.x * 32;
    const int b   = blockIdx.y;
    const int tid = threadIdx.x;

    for (int i = tid; i < CIN * 34 * TT; i += 256) {
        int c   = i / (34 * TT);
        int rem = i % (34 * TT);
        int lx  = rem / TT;
        int t   = rem % TT;
        int gl  = l0 - 1 + lx;
        float v = 0.0f;
        if (gl >= 0 && gl < LL)
            v = x[((size_t)(b * CIN + c) * LL + gl) * TT + t];
        s_x[c][lx][t] = v;
    }

    const int w    = tid >> 5;
    const int lane = tid & 31;
    const int half = w & 1;
    const int pair = w >> 1;
    const int c1   = half * 32 + lane;

    ull wrp[CIN][3];
#pragma unroll
    for (int c = 0; c < CIN; c++)
#pragma unroll
        for (int k = 0; k < 3; k++) {
            float wv = w1[c1 * (CIN * 3) + c * 3 + k];
            PACK_F32X2(wrp[c][k], wv, wv);
        }
    const float bias = b1[c1];
    const float gain = *pgain;
    const float th1  = *pth1;

    __syncthreads();

    for (int task = pair; task < 160; task += 4) {
        int ll = task & 31;
        int tg = task >> 5;
        int t0 = tg * 4;
        ull a01 = 0ull, a23 = 0ull;
#pragma unroll
        for (int c = 0; c < CIN; c++) {
#pragma unroll
            for (int k = 0; k < 3; k++) {
                ulonglong2 xq = *(const ulonglong2*)&s_x[c][ll + k][t0];
                FMA_F32X2(a01, xq.x, wrp[c][k], a01);
                FMA_F32X2(a23, xq.y, wrp[c][k], a23);
            }
        }
        float a[4];
        UNPACK_F32X2(a[0], a[1], a01);
        UNPACK_F32X2(a[2], a[3], a23);
        int gl = l0 + ll;
#pragma unroll
        for (int j = 0; j < 4; j++) {
            float i1 = (a[j] + bias) * gain;
            unsigned m = __ballot_sync(0xffffffffu, i1 >= th1);
            if (lane == 0)
                g_s1[((size_t)(b * TT + (t0 + j)) * LL + gl) * 2 + half] = m;
        }
    }
}

// ---------------------------------------------------------------------------
// k_snn: conv2 via mma.sync (HMMA) + LIF, accumulators & state in registers.
// CTA = (b, 128-l tile), 512 threads = 16 warps.
// warp = m-tile j (w&3: 16 c2 rows, hi + matching lo plane) x n-quarter q
// (w>>2: 32 l). Per t: decode spikes -> fragment-ordered bf16 B in smem;
// 12 k-steps x 4 n-tiles x {hi,lo} mma; LIF on fp32 fragments in registers.
// ---------------------------------------------------------------------------
__device__ __forceinline__ u32 pack_bits2(u32 q, int p) {
    u32 r = q >> p;
    return (r & 1u) * 0x3F80u + ((r >> 1) & 1u) * 0x3F800000u;
}

__global__ __launch_bounds__(512, 1) void k_snn(
        const float* __restrict__ b2,
        const float* __restrict__ pgain,
        const float* __restrict__ pth2) {
    extern __shared__ __align__(16) u32 smw[];
    u32* Ash = smw;                 // 6144 u32 = 24 KB
    u32* Asl = smw + 6144;          // 24 KB
    uint2* Bs = (uint2*)(smw + 12288);  // [s][n][tig] uint2 -> 48 KB

    const int tid = threadIdx.x;
    const int b   = blockIdx.x >> 5;        // / NTILES
    const int l0  = (blockIdx.x & 31) * NLT;

    // stage A fragments (L2-hot, same for every CTA)
    for (int i = tid; i < 6144; i += 512) {
        Ash[i] = g_Ah[i];
        Asl[i] = g_Al[i];
    }

    const int w    = tid >> 5;
    const int lane = tid & 31;
    const int j    = w & 3;       // m-tile (16 c2 rows)
    const int q    = w >> 2;      // n-quarter (32 l)
    const int gid  = lane >> 2;
    const int tid4 = lane & 3;

    const float gain   = *pgain;
    const float th2    = *pth2;
    const float invtau = 1.0f / 0.9f;
    const float bia0   = b2[16 * j + gid];
    const float bia1   = b2[16 * j + gid + 8];

    float v2[16], cnt[16];
#pragma unroll
    for (int i = 0; i < 16; i++) { v2[i] = 0.0f; cnt[i] = 0.0f; }

    __syncthreads();

    for (int t = 0; t < TT; t++) {
        // ---- decode spike bits -> fragment-ordered bf16 B tile ----
#pragma unroll
        for (int i = 0; i < 3; i++) {
            int task = tid + 512 * i;       // 0..1535
            int s  = task >> 7;
            int n  = task & 127;
            int kk = s >> 2;
            int h  = (s >> 1) & 1;
            int bs = (s & 1) * 16;
            int gl = l0 + n + kk - 1;
            u32 m = 0;
            if (gl >= 0 && gl < LL)
                m = g_s1[((size_t)(b * TT + t) * LL + gl) * 2 + h];
            u32 qq = m >> bs;
            uint4 v0, v1;
            v0.x = pack_bits2(qq, 0);  v0.y = pack_bits2(qq, 8);
            v0.z = pack_bits2(qq, 2);  v0.w = pack_bits2(qq, 10);
            v1.x = pack_bits2(qq, 4);  v1.y = pack_bits2(qq, 12);
            v1.z = pack_bits2(qq, 6);  v1.w = pack_bits2(qq, 14);
            uint4* dst = (uint4*)&Bs[(s * 128 + n) * 4];
            dst[0] = v0;
            dst[1] = v1;
        }
        __syncthreads();

        // ---- mma: D[c2_hi|c2_lo][l] = A * B ----
        float acc_h[4][4], acc_l[4][4];
#pragma unroll
        for (int nt = 0; nt < 4; nt++)
#pragma unroll
            for (int r = 0; r < 4; r++) { acc_h[nt][r] = 0.0f; acc_l[nt][r] = 0.0f; }

#pragma unroll
        for (int s = 0; s < 12; s++) {
            uint4 ah = *(const uint4*)&Ash[((j * 12 + s) * 32 + lane) * 4];
            uint4 al = *(const uint4*)&Asl[((j * 12 + s) * 32 + lane) * 4];
#pragma unroll
            for (int nt = 0; nt < 4; nt++) {
                int n = q * 32 + nt * 8 + gid;
                uint2 bb = Bs[(s * 128 + n) * 4 + tid4];
                MMA16816(acc_h[nt], ah, bb);
                MMA16816(acc_l[nt], al, bb);
            }
        }

        // ---- LIF epilogue, all in registers ----
#pragma unroll
        for (int nt = 0; nt < 4; nt++)
#pragma unroll
            for (int r = 0; r < 4; r++) {
                float sfull = acc_h[nt][r] + acc_l[nt][r];
                float bia = (r >> 1) ? bia1 : bia0;   // D rows: r<2 -> gid, r>=2 -> gid+8
                float i2 = (sfull + bia) * gain;
                int idx = nt * 4 + r;
                v2[idx] += (i2 - v2[idx]) * invtau;
                if (v2[idx] >= th2) { cnt[idx] += 1.0f; v2[idx] = 0.0f; }
            }
        __syncthreads();   // B consumed before next decode overwrites
    }

    // ---- pool: sum counts per c2 ----
    float t0 = 0.0f, t1 = 0.0f;
#pragma unroll
    for (int nt = 0; nt < 4; nt++)
#pragma unroll
        for (int r = 0; r < 4; r++) {
            if (r >> 1) t1 += cnt[nt * 4 + r];
            else        t0 += cnt[nt * 4 + r];
        }
    // reduce over tid4 (same c2 across the 4 lanes of a quad)
    t0 += __shfl_xor_sync(0xffffffffu, t0, 1);
    t0 += __shfl_xor_sync(0xffffffffu, t0, 2);
    t1 += __shfl_xor_sync(0xffffffffu, t1, 1);
    t1 += __shfl_xor_sync(0xffffffffu, t1, 2);
    if (tid4 == 0) {
        atomicAdd(&g_pool[b * NC2 + 16 * j + gid],     t0);   // integer-valued
        atomicAdd(&g_pool[b * NC2 + 16 * j + gid + 8], t1);
    }
}

// ---------------------------------------------------------------------------
// k_fc: pooled = counts / (T*L); logits = pooled @ fc_w.T + fc_b
// ---------------------------------------------------------------------------
__global__ void k_fc(const float* __restrict__ fw,
                     const float* __restrict__ fb,
                     float* __restrict__ out) {
    int tid = threadIdx.x;
    int b = tid >> 2;
    int n = tid & 3;
    const float sc = 1.0f / (float)(TT * LL);
    float s = fb[n];
#pragma unroll
    for (int c = 0; c < NC2; c++)
        s += (g_pool[b * NC2 + c] * sc) * fw[n * NC2 + c];
    out[b * NCLS + n] = s;
}

// ---------------------------------------------------------------------------
#define SNN_SMEM (12288 * 4 + 49152)   // 98304 bytes

extern "C" void kernel_launch(void* const* d_in, const int* in_sizes, int n_in,
                              void* d_out, int out_size) {
    const float* x    = (const float*)d_in[0];
    const float* w1   = (const float*)d_in[1];
    const float* b1   = (const float*)d_in[2];
    const float* w2   = (const float*)d_in[3];
    const float* b2   = (const float*)d_in[4];
    const float* gain = (const float*)d_in[5];
    const float* th1  = (const float*)d_in[6];
    const float* th2  = (const float*)d_in[7];
    const float* fw   = (const float*)d_in[8];
    const float* fb   = (const float*)d_in[9];
    float* out = (float*)d_out;

    cudaFuncSetAttribute(k_snn, cudaFuncAttributeMaxDynamicSharedMemorySize,
                         SNN_SMEM);

    k_pre<<<24, 256>>>(w2);

    dim3 g1(LL / 32, BB);
    k_conv1<<<g1, 256>>>(x, w1, b1, gain, th1);

    k_snn<<<BB * NTILES, 512, SNN_SMEM>>>(b2, gain, th2);

    k_fc<<<1, 256>>>(fw, fb, out);
}

// round 6
// speedup vs baseline: 4.5882x; 1.1859x over previous
#include <cuda_runtime.h>
#include <cuda_bf16.h>
#include <cstdint>

#define BB   64
#define CIN  12
#define LL   4096
#define TT   20
#define NC1  64
#define NC2  64
#define NCLS 4
#define NLT  128                 // l positions per tile
#define NTILES (LL / NLT)        // 32
#define NBP  132                 // padded B rows (130 used)

typedef unsigned long long ull;
typedef unsigned int u32;

// spike bits: 2x u32 per (b,t,l)  => 41.9 MB scratch
__device__ u32 g_s1[BB * TT * LL * 2];
// per (b,c2) spike counts
__device__ float g_pool[BB * NC2];
// A fragments (K=64, per-tap), exact mma lane order: [((j*3+kk)*4+s)*32+lane]*4+r
__device__ u32 g_Ah[4 * 3 * 4 * 32 * 4];   // 6144 u32
__device__ u32 g_Al[4 * 3 * 4 * 32 * 4];

// ---------------- packed f32x2 helpers (conv1) ------------------------------
#define FMA_F32X2(d, a, b, c) \
    asm("fma.rn.f32x2 %0, %1, %2, %3;" : "=l"(d) : "l"(a), "l"(b), "l"(c))
#define PACK_F32X2(out, lo, hi) \
    asm("mov.b64 %0, {%1, %2};" : "=l"(out) : "f"(lo), "f"(hi))
#define UNPACK_F32X2(lo, hi, in) \
    asm("mov.b64 {%0, %1}, %2;" : "=f"(lo), "=f"(hi) : "l"(in))

// mma.sync m16n8k16 bf16, fp32 accumulate (baseline PTX, sm_80+)
#define MMA16816(d, a, b) \
    asm volatile("mma.sync.aligned.m16n8k16.row.col.f32.bf16.bf16.f32 " \
        "{%0,%1,%2,%3}, {%4,%5,%6,%7}, {%8,%9}, {%0,%1,%2,%3};" \
        : "+f"((d)[0]), "+f"((d)[1]), "+f"((d)[2]), "+f"((d)[3]) \
        : "r"((a).x), "r"((a).y), "r"((a).z), "r"((a).w), \
          "r"((b).x), "r"((b).y))

// channel permutation chosen so decode is a single multiply-spread:
// out[i] of spike word m_h = bits (i, i+16) -> k-positions (2a, 2a+1), a = h*16+i
__device__ __host__ __forceinline__ int chan_for_k(int kappa) {
    int a  = kappa >> 1;
    int hh = a >> 4;
    int ii = a & 15;
    return hh * 32 + ii + ((kappa & 1) << 4);
}

// ---------------------------------------------------------------------------
// k_pre: zero pool + build per-tap A fragments (hi/lo bf16 split, exact)
// ---------------------------------------------------------------------------
__global__ void k_pre(const float* __restrict__ w2) {
    int i = blockIdx.x * blockDim.x + threadIdx.x;
    if (i < BB * NC2) g_pool[i] = 0.0f;
    if (i < 6144) {
        int r    = i & 3;
        int idx4 = i >> 2;
        int lane = idx4 & 31;
        int rest = idx4 >> 5;        // (j*3+kk)*4 + s
        int s    = rest & 3;
        int kkj  = rest >> 2;
        int kk   = kkj % 3;
        int j    = kkj / 3;
        int gid  = lane >> 2;
        int t4   = lane & 3;
        int m    = 16 * j + gid + 8 * (r & 1);
        u32 hi = 0, lo = 0;
#pragma unroll
        for (int e = 0; e < 2; e++) {
            int kappa = 16 * s + 2 * t4 + 8 * (r >> 1) + e;
            int c1    = chan_for_k(kappa);
            float wv  = w2[m * (NC1 * 3) + c1 * 3 + kk];
            __nv_bfloat16 bh = __float2bfloat16(wv);
            __nv_bfloat16 bl = __float2bfloat16(wv - __bfloat162float(bh));
            hi |= (u32)__bfloat16_as_ushort(bh) << (16 * e);
            lo |= (u32)__bfloat16_as_ushort(bl) << (16 * e);
        }
        g_Ah[i] = hi;
        g_Al[i] = lo;
    }
}

// ---------------------------------------------------------------------------
// k_conv1: conv1 + threshold -> bit-packed spikes (TAU1=1 => stateless).
// (unchanged: packed f32x2 over contiguous t axis)
// ---------------------------------------------------------------------------
__global__ __launch_bounds__(256) void k_conv1(
        const float* __restrict__ x,
        const float* __restrict__ w1,
        const float* __restrict__ b1,
        const float* __restrict__ pgain,
        const float* __restrict__ pth1) {
    __shared__ __align__(16) float s_x[CIN][34][TT];

    const int l0  = blockIdx.x * 32;
    const int b   = blockIdx.y;
    const int tid = threadIdx.x;

    for (int i = tid; i < CIN * 34 * TT; i += 256) {
        int c   = i / (34 * TT);
        int rem = i % (34 * TT);
        int lx  = rem / TT;
        int t   = rem % TT;
        int gl  = l0 - 1 + lx;
        float v = 0.0f;
        if (gl >= 0 && gl < LL)
            v = x[((size_t)(b * CIN + c) * LL + gl) * TT + t];
        s_x[c][lx][t] = v;
    }

    const int w    = tid >> 5;
    const int lane = tid & 31;
    const int half = w & 1;
    const int pair = w >> 1;
    const int c1   = half * 32 + lane;

    ull wrp[CIN][3];
#pragma unroll
    for (int c = 0; c < CIN; c++)
#pragma unroll
        for (int k = 0; k < 3; k++) {
            float wv = w1[c1 * (CIN * 3) + c * 3 + k];
            PACK_F32X2(wrp[c][k], wv, wv);
        }
    const float bias = b1[c1];
    const float gain = *pgain;
    const float th1  = *pth1;

    __syncthreads();

    for (int task = pair; task < 160; task += 4) {
        int ll = task & 31;
        int tg = task >> 5;
        int t0 = tg * 4;
        ull a01 = 0ull, a23 = 0ull;
#pragma unroll
        for (int c = 0; c < CIN; c++) {
#pragma unroll
            for (int k = 0; k < 3; k++) {
                ulonglong2 xq = *(const ulonglong2*)&s_x[c][ll + k][t0];
                FMA_F32X2(a01, xq.x, wrp[c][k], a01);
                FMA_F32X2(a23, xq.y, wrp[c][k], a23);
            }
        }
        float a[4];
        UNPACK_F32X2(a[0], a[1], a01);
        UNPACK_F32X2(a[2], a[3], a23);
        int gl = l0 + ll;
#pragma unroll
        for (int j = 0; j < 4; j++) {
            float i1 = (a[j] + bias) * gain;
            unsigned m = __ballot_sync(0xffffffffu, i1 >= th1);
            if (lane == 0)
                g_s1[((size_t)(b * TT + (t0 + j)) * LL + gl) * 2 + half] = m;
        }
    }
}

// ---------------------------------------------------------------------------
// k_snn: conv2 via mma.sync, K=64 with 3 shifted-B accumulating taps.
// CTA = (b, 128-l tile), 512 threads = 16 warps.
// warp = m-tile j (w&3) x n-quarter q (w>>2). B tile [130n x 64k] bf16,
// double-buffered (4.2 KB each); decode = 1 multiply per 2 channels;
// hi & lo planes chain into the same accumulator; LIF all in registers.
// smem u32 layout: Ash[0..6144), Asl[6144..12288), Bs[12288 + p*4224 ...)
// ---------------------------------------------------------------------------
#define SNN_SMEM ((12288 + 2 * 4224) * 4)     // 82944 bytes

__global__ __launch_bounds__(512, 1) void k_snn(
        const float* __restrict__ b2,
        const float* __restrict__ pgain,
        const float* __restrict__ pth2) {
    extern __shared__ __align__(16) u32 smw[];
    u32* Ash = smw;
    u32* Asl = smw + 6144;
    u32* Bs  = smw + 12288;

    const int tid = threadIdx.x;
    const int b   = blockIdx.x >> 5;
    const int l0  = (blockIdx.x & 31) * NLT;

    // stage A fragments (L2-hot, identical for every CTA)
    for (int i = tid; i < 1536; i += 512) {
        ((uint4*)Ash)[i] = ((const uint4*)g_Ah)[i];
        ((uint4*)Asl)[i] = ((const uint4*)g_Al)[i];
    }

    const int w    = tid >> 5;
    const int lane = tid & 31;
    const int j    = w & 3;       // m-tile (16 c2 rows)
    const int q    = w >> 2;      // n-quarter (32 l)
    const int gid  = lane >> 2;
    const int tid4 = lane & 3;

    const float gain   = *pgain;
    const float th2    = *pth2;
    const float invtau = 1.0f / 0.9f;
    const float bia0   = b2[16 * j + gid];
    const float bia1   = b2[16 * j + gid + 8];

    // decode task assignment (260 tasks over 512 threads)
    const bool dact = tid < 260;
    int dh = 0, dn = 0;
    bool inrange = false;
    size_t gstep = 0, gaddr = 0;
    if (dact) {
        dh = (tid >= 130) ? 1 : 0;
        dn = tid - 130 * dh;
        int gl  = l0 - 1 + dn;
        inrange = (gl >= 0 && gl < LL);
        if (inrange) {
            gaddr = ((size_t)(b * TT) * LL + gl) * 2 + dh;
            gstep = (size_t)LL * 2;
        }
    }

    float v2[16], cnt[16];
#pragma unroll
    for (int i = 0; i < 16; i++) { v2[i] = 0.0f; cnt[i] = 0.0f; }

    u32 m_next = 0;
    if (dact && inrange) m_next = g_s1[gaddr];

    __syncthreads();

    for (int t = 0; t < TT; t++) {
        const int p = t & 1;
        u32* Bp = Bs + p * 4224;

        // ---- decode spikes for t; prefetch t+1 ----
        u32 mcur = m_next;
        if (dact && inrange && t + 1 < TT)
            m_next = g_s1[gaddr + (size_t)(t + 1) * gstep];
        if (dact) {
            u32 o[16];
#pragma unroll
            for (int i = 0; i < 16; i++)
                o[i] = ((mcur >> i) & 0x00010001u) * 0x3F80u;
            u32* r0 = Bp + ((2 * dh)     * NBP + dn) * 8;
            u32* r1 = Bp + ((2 * dh + 1) * NBP + dn) * 8;
            ((uint4*)r0)[0] = make_uint4(o[0],  o[4],  o[1],  o[5]);
            ((uint4*)r0)[1] = make_uint4(o[2],  o[6],  o[3],  o[7]);
            ((uint4*)r1)[0] = make_uint4(o[8],  o[12], o[9],  o[13]);
            ((uint4*)r1)[1] = make_uint4(o[10], o[14], o[11], o[15]);
        }
        __syncthreads();

        // ---- mma: 4 k-steps x 3 taps x 4 n-tiles, hi+lo chained ----
        float acc[4][4];
#pragma unroll
        for (int nt = 0; nt < 4; nt++)
#pragma unroll
            for (int r = 0; r < 4; r++) acc[nt][r] = 0.0f;

#pragma unroll
        for (int s = 0; s < 4; s++) {
#pragma unroll
            for (int kk = 0; kk < 3; kk++) {
                int abase = (((j * 3 + kk) * 4 + s) * 32 + lane) * 4;
                uint4 ah = *(const uint4*)&Ash[abase];
                uint4 al = *(const uint4*)&Asl[abase];
#pragma unroll
                for (int nt = 0; nt < 4; nt++) {
                    int nrow = q * 32 + nt * 8 + gid + kk;
                    uint2 bb = *(const uint2*)&Bp[(s * NBP + nrow) * 8 + tid4 * 2];
                    MMA16816(acc[nt], ah, bb);
                    MMA16816(acc[nt], al, bb);
                }
            }
        }

        // ---- LIF epilogue, all in registers ----
#pragma unroll
        for (int nt = 0; nt < 4; nt++)
#pragma unroll
            for (int r = 0; r < 4; r++) {
                float bia = (r >> 1) ? bia1 : bia0;
                float i2  = (acc[nt][r] + bia) * gain;
                int idx = nt * 4 + r;
                v2[idx] += (i2 - v2[idx]) * invtau;
                if (v2[idx] >= th2) { cnt[idx] += 1.0f; v2[idx] = 0.0f; }
            }
    }

    // ---- pool: sum counts per c2 ----
    float t0 = 0.0f, t1 = 0.0f;
#pragma unroll
    for (int nt = 0; nt < 4; nt++)
#pragma unroll
        for (int r = 0; r < 4; r++) {
            if (r >> 1) t1 += cnt[nt * 4 + r];
            else        t0 += cnt[nt * 4 + r];
        }
    t0 += __shfl_xor_sync(0xffffffffu, t0, 1);
    t0 += __shfl_xor_sync(0xffffffffu, t0, 2);
    t1 += __shfl_xor_sync(0xffffffffu, t1, 1);
    t1 += __shfl_xor_sync(0xffffffffu, t1, 2);
    if (tid4 == 0) {
        atomicAdd(&g_pool[b * NC2 + 16 * j + gid],     t0);   // integer-valued
        atomicAdd(&g_pool[b * NC2 + 16 * j + gid + 8], t1);
    }
}

// ---------------------------------------------------------------------------
// k_fc: pooled = counts / (T*L); logits = pooled @ fc_w.T + fc_b
// ---------------------------------------------------------------------------
__global__ void k_fc(const float* __restrict__ fw,
                     const float* __restrict__ fb,
                     float* __restrict__ out) {
    int tid = threadIdx.x;
    int b = tid >> 2;
    int n = tid & 3;
    const float sc = 1.0f / (float)(TT * LL);
    float s = fb[n];
#pragma unroll
    for (int c = 0; c < NC2; c++)
        s += (g_pool[b * NC2 + c] * sc) * fw[n * NC2 + c];
    out[b * NCLS + n] = s;
}

// ---------------------------------------------------------------------------
extern "C" void kernel_launch(void* const* d_in, const int* in_sizes, int n_in,
                              void* d_out, int out_size) {
    const float* x    = (const float*)d_in[0];
    const float* w1   = (const float*)d_in[1];
    const float* b1   = (const float*)d_in[2];
    const float* w2   = (const float*)d_in[3];
    const float* b2   = (const float*)d_in[4];
    const float* gain = (const float*)d_in[5];
    const float* th1  = (const float*)d_in[6];
    const float* th2  = (const float*)d_in[7];
    const float* fw   = (const float*)d_in[8];
    const float* fb   = (const float*)d_in[9];
    float* out = (float*)d_out;

    cudaFuncSetAttribute(k_snn, cudaFuncAttributeMaxDynamicSharedMemorySize,
                         SNN_SMEM);

    k_pre<<<24, 256>>>(w2);

    dim3 g1(LL / 32, BB);
    k_conv1<<<g1, 256>>>(x, w1, b1, gain, th1);

    k_snn<<<BB * NTILES, 512, SNN_SMEM>>>(b2, gain, th2);

    k_fc<<<1, 256>>>(fw, fb, out);
}